// round 14
// baseline (speedup 1.0000x reference)
#include <cuda_runtime.h>
#include <cuda_fp16.h>
#include <mma.h>
#include <math.h>

using namespace nvcuda;

#define DIMC   768
#define HEADSC 12
#define HDC    64
#define BC     2
#define NC     1024
#define MLPC   3072
#define ROWS   (BC * NC)
#define NN     (NC * NC)
#define SCALEC 0.125f
#define NSPLIT 4

// ---------------- scratch ----------------
__device__ __half g_h   [ROWS * DIMC];
__device__ __half g_qkvh[ROWS * 3 * DIMC];
__device__ __half g_qk  [(size_t)BC * HEADSC * NN];
__device__ __half g_attn[(size_t)BC * HEADSC * NN];
__device__ __half g_av  [ROWS * DIMC];
__device__ float  g_x1  [ROWS * DIMC];
__device__ __half g_h2  [ROWS * DIMC];
__device__ __half g_fc1 [ROWS * MLPC];
__device__ float  g_fc2p[NSPLIT * ROWS * DIMC];
__device__ __half g_wqkv[3 * DIMC * DIMC];
__device__ __half g_wpro[DIMC * DIMC];
__device__ __half g_wfc1[MLPC * DIMC];
__device__ __half g_wfc2[DIMC * MLPC];

// ---------------- fused weight fp32->fp16 ----------------
#define W0 (3 * DIMC * DIMC)
#define W1 (DIMC * DIMC)
#define W2 (MLPC * DIMC)
#define W3 (DIMC * MLPC)
__global__ void f2h_all(const float* __restrict__ a, const float* __restrict__ b,
                        const float* __restrict__ c, const float* __restrict__ d,
                        __half* __restrict__ oa, __half* __restrict__ ob,
                        __half* __restrict__ oc, __half* __restrict__ od) {
    size_t i4 = (size_t)blockIdx.x * 256 + threadIdx.x;
    size_t i  = i4 * 4;
    const float* src; __half* dst; size_t off;
    if (i < W0)                { src = a; dst = oa; off = i; }
    else if (i < W0 + W1)      { src = b; dst = ob; off = i - W0; }
    else if (i < W0 + W1 + W2) { src = c; dst = oc; off = i - W0 - W1; }
    else if (i < W0 + W1 + W2 + W3) { src = d; dst = od; off = i - W0 - W1 - W2; }
    else return;
    float4 v = *(const float4*)(src + off);
    __half2* o2 = (__half2*)(dst + off);
    o2[0] = __floats2half2_rn(v.x, v.y);
    o2[1] = __floats2half2_rn(v.z, v.w);
}

// ---------------- layernorm (half out) ----------------
__global__ void ln_kernel(const float* __restrict__ x, const float* __restrict__ g,
                          const float* __restrict__ b, __half* __restrict__ y) {
    int row = blockIdx.x;
    const float* xr = x + (size_t)row * DIMC;
    __half*      yr = y + (size_t)row * DIMC;
    float v[3];
    float s = 0.f, s2 = 0.f;
#pragma unroll
    for (int i = 0; i < 3; i++) {
        v[i] = xr[threadIdx.x + 256 * i];
        s += v[i]; s2 += v[i] * v[i];
    }
    __shared__ float sh[16];
#pragma unroll
    for (int o = 16; o; o >>= 1) {
        s  += __shfl_xor_sync(~0u, s,  o);
        s2 += __shfl_xor_sync(~0u, s2, o);
    }
    int w = threadIdx.x >> 5;
    if ((threadIdx.x & 31) == 0) { sh[w] = s; sh[8 + w] = s2; }
    __syncthreads();
    if (threadIdx.x < 32) {
        s  = threadIdx.x < 8 ? sh[threadIdx.x]     : 0.f;
        s2 = threadIdx.x < 8 ? sh[8 + threadIdx.x] : 0.f;
#pragma unroll
        for (int o = 4; o; o >>= 1) {
            s  += __shfl_xor_sync(~0u, s,  o);
            s2 += __shfl_xor_sync(~0u, s2, o);
        }
        if (threadIdx.x == 0) { sh[0] = s; sh[1] = s2; }
    }
    __syncthreads();
    float mean = sh[0] * (1.f / DIMC);
    float var  = sh[1] * (1.f / DIMC) - mean * mean;
    float rstd = rsqrtf(var + 1e-5f);
#pragma unroll
    for (int i = 0; i < 3; i++) {
        int c = threadIdx.x + 256 * i;
        yr[c] = __float2half_rn((v[i] - mean) * rstd * g[c] + b[c]);
    }
}

// ------ fused middle v2: no max pass; exp cached in smem ------
// one block per (b, n); 256 threads x 4 m-positions x 12 heads.
__global__ __launch_bounds__(256)
void mid_kernel(const __half* __restrict__ qk, const float* __restrict__ r,
                const float* __restrict__ cw, const float* __restrict__ cb,
                float* __restrict__ am, float* __restrict__ unc,
                __half* __restrict__ attn) {
    extern __shared__ float sm[];
    float* se  = sm;                         // [12][256][4] exps, 12288 floats
    float* scw = sm + HEADSC * 256 * 4;      // 144
    float* scb = scw + HEADSC * HEADSC;      // 12
    float* red = scb + HEADSC;               // 96
    float* fnv = red + 8 * HEADSC;           // 12

    int t  = threadIdx.x;
    int bn = blockIdx.x;
    int b  = bn >> 10, n = bn & 1023;
    if (t < HEADSC * HEADSC) scw[t] = cw[t];
    if (t < HEADSC)          scb[t] = cb[t];

    size_t base = (((size_t)b * HEADSC) << 20) + ((size_t)n << 10) + t * 4;

    float4 sv[HEADSC];
#pragma unroll
    for (int h = 0; h < HEADSC; h++) {
        const __half2* qp = (const __half2*)(qk + base + ((size_t)h << 20));
        __half2 q0 = qp[0], q1 = qp[1];
        float2 f0 = __half22float2(q0), f1 = __half22float2(q1);
        sv[h] = make_float4(f0.x, f0.y, f1.x, f1.y);
    }

    // exp + per-head sum (no max subtraction: |s*SCALE| small, fp32-safe)
#pragma unroll
    for (int h = 0; h < HEADSC; h++) {
        float4 e;
        e.x = __expf(sv[h].x * SCALEC);
        e.y = __expf(sv[h].y * SCALEC);
        e.z = __expf(sv[h].z * SCALEC);
        e.w = __expf(sv[h].w * SCALEC);
        *(float4*)&se[(h * 256 + t) * 4] = e;
        float s = e.x + e.y + e.z + e.w;
#pragma unroll
        for (int o = 16; o; o >>= 1) s += __shfl_xor_sync(~0u, s, o);
        if ((t & 31) == 0) red[(t >> 5) * HEADSC + h] = s;
    }
    __syncthreads();
    if (t < HEADSC) {
        float s = 0.f;
#pragma unroll
        for (int ww = 0; ww < 8; ww++) s += red[ww * HEADSC + t];
        fnv[t] = 1.f / s;
    }
    __syncthreads();

    // outputs: conv over heads + sigmoid + softmax write (cached exps) + attn
#pragma unroll
    for (int g = 0; g < HEADSC; g++) {
        float ax = scb[g], ay = scb[g], az = scb[g], aw = scb[g];
#pragma unroll
        for (int h = 0; h < HEADSC; h++) {
            float wv = scw[g * HEADSC + h];
            ax += wv * sv[h].x; ay += wv * sv[h].y;
            az += wv * sv[h].z; aw += wv * sv[h].w;
        }
        float4 u;
        u.x = 1.f / (1.f + __expf(-ax));
        u.y = 1.f / (1.f + __expf(-ay));
        u.z = 1.f / (1.f + __expf(-az));
        u.w = 1.f / (1.f + __expf(-aw));
        float iv = fnv[g];
        float4 e = *(const float4*)&se[(g * 256 + t) * 4];
        float4 p;
        p.x = e.x * iv; p.y = e.y * iv; p.z = e.z * iv; p.w = e.w * iv;
        size_t o = base + ((size_t)g << 20);
        float4 rv = *(const float4*)(r + o);
        *(float4*)(am + o)  = p;
        *(float4*)(unc + o) = u;
        __half2* at = (__half2*)(attn + o);
        at[0] = __floats2half2_rn(p.x + u.x * rv.x, p.y + u.y * rv.y);
        at[1] = __floats2half2_rn(p.z + u.z * rv.z, p.w + u.w * rv.w);
    }
}

// ------ split-K reduce ------
__global__ void fc2_reduce_kernel(const float* __restrict__ part,
                                  const float* __restrict__ x1,
                                  const float* __restrict__ bias,
                                  float* __restrict__ out) {
    size_t i = ((size_t)blockIdx.x * 256 + threadIdx.x) * 4;
    int col = (int)(i % DIMC);
    float4 v  = *(const float4*)(x1 + i);
    float4 bv = *(const float4*)(bias + col);
    v.x += bv.x; v.y += bv.y; v.z += bv.z; v.w += bv.w;
#pragma unroll
    for (int s = 0; s < NSPLIT; s++) {
        float4 p = *(const float4*)(part + (size_t)s * ROWS * DIMC + i);
        v.x += p.x; v.y += p.y; v.z += p.z; v.w += p.w;
    }
    *(float4*)(out + i) = v;
}

// ---------------- fp16 tensor-core GEMM (2-stage cp.async, templated BK) ----------------
__device__ __forceinline__ void cpa16h(__half* dst, const __half* src) {
    unsigned s = (unsigned)__cvta_generic_to_shared(dst);
    asm volatile("cp.async.cg.shared.global [%0], [%1], 16;" :: "r"(s), "l"(src));
}

template<int BK, int BN, int BLAY, int EPI, int OUTH>
__global__ __launch_bounds__(256)
void gemm_h(const __half* __restrict__ A, const __half* __restrict__ B,
            void* __restrict__ Cv, const float* __restrict__ bias,
            const float* __restrict__ res,
            int K, int lda, int ldb, int ldc,
            long sAb, long sAh, long sBb, long sBh, long sCb, long sCh,
            int Hdiv) {
    constexpr int BM  = 128;
    constexpr int LDS = BK + 8;
    constexpr int WN  = BN / 2;
    constexpr int NFR = WN / 16;
    constexpr int ASZ = BM * LDS;
    constexpr int LDB_S = (BLAY == 0) ? LDS : (BN + 8);
    constexpr int BSZ = (BLAY == 0) ? BN * LDS : BK * LDB_S;
    constexpr int CPR = BK / 8;

    extern __shared__ __half smem[];
    __half* As[2] = { smem,       smem + ASZ + BSZ };
    __half* Bs[2] = { smem + ASZ, smem + 2 * ASZ + BSZ };

    int z  = blockIdx.z;
    int zb = z / Hdiv, zh = z % Hdiv;
    A += zb * sAb + zh * sAh;
    B += zb * sBb + zh * sBh;
    size_t coff = (size_t)zb * sCb + (size_t)zh * sCh;
    float*  Cf = (float*)Cv + coff;
    __half* Ch = (__half*)Cv + coff;
    if (EPI == 3) res += coff;

    int m0 = blockIdx.y * BM, n0 = blockIdx.x * BN;
    int t   = threadIdx.x;
    int wid = t >> 5;
    int wm  = wid & 3;
    int wn  = wid >> 2;

    wmma::fragment<wmma::accumulator, 16, 16, 16, float> acc[2][NFR];
#pragma unroll
    for (int i = 0; i < 2; i++)
#pragma unroll
        for (int j = 0; j < NFR; j++) wmma::fill_fragment(acc[i][j], 0.f);

    const int stages = K / BK;

    auto load_tiles = [&](int k0, int st) {
#pragma unroll
        for (int i = 0; i < BM * BK / 8 / 256; i++) {
            int f   = t + i * 256;
            int row = f / CPR;
            int c8  = (f % CPR) * 8;
            cpa16h(As[st] + row * LDS + c8,
                   A + (size_t)(m0 + row) * lda + k0 + c8);
        }
        if (BLAY == 0) {
#pragma unroll
            for (int i = 0; i < BN * BK / 8 / 256; i++) {
                int f   = t + i * 256;
                int row = f / CPR;
                int c8  = (f % CPR) * 8;
                cpa16h(Bs[st] + row * LDS + c8,
                       B + (size_t)(n0 + row) * ldb + k0 + c8);
            }
        } else {
#pragma unroll
            for (int i = 0; i < BK * BN / 8 / 256; i++) {
                int f   = t + i * 256;
                int row = f / (BN / 8);
                int c8  = (f % (BN / 8)) * 8;
                cpa16h(Bs[st] + row * LDB_S + c8,
                       B + (size_t)(k0 + row) * ldb + n0 + c8);
            }
        }
        asm volatile("cp.async.commit_group;" ::: "memory");
    };

    load_tiles(0, 0);

    for (int it = 0; it < stages; ++it) {
        int cur = it & 1;
        if (it + 1 < stages) {
            load_tiles((it + 1) * BK, cur ^ 1);
            asm volatile("cp.async.wait_group 1;" ::: "memory");
        } else {
            asm volatile("cp.async.wait_group 0;" ::: "memory");
        }
        __syncthreads();

        const __half* as = As[cur];
        const __half* bs = Bs[cur];
#pragma unroll
        for (int kk = 0; kk < BK; kk += 16) {
            wmma::fragment<wmma::matrix_a, 16, 16, 16, __half, wmma::row_major> af[2];
#pragma unroll
            for (int i = 0; i < 2; i++)
                wmma::load_matrix_sync(af[i], as + (wm * 32 + i * 16) * LDS + kk, LDS);
            if (BLAY == 0) {
#pragma unroll
                for (int j = 0; j < NFR; j++) {
                    wmma::fragment<wmma::matrix_b, 16, 16, 16, __half, wmma::col_major> bf;
                    wmma::load_matrix_sync(bf, bs + (wn * WN + j * 16) * LDS + kk, LDS);
#pragma unroll
                    for (int i = 0; i < 2; i++)
                        wmma::mma_sync(acc[i][j], af[i], bf, acc[i][j]);
                }
            } else {
#pragma unroll
                for (int j = 0; j < NFR; j++) {
                    wmma::fragment<wmma::matrix_b, 16, 16, 16, __half, wmma::row_major> bf;
                    wmma::load_matrix_sync(bf, bs + kk * LDB_S + wn * WN + j * 16, LDB_S);
#pragma unroll
                    for (int i = 0; i < 2; i++)
                        wmma::mma_sync(acc[i][j], af[i], bf, acc[i][j]);
                }
            }
        }
        __syncthreads();
    }

    if (EPI == 0 && OUTH == 0) {
#pragma unroll
        for (int i = 0; i < 2; i++)
#pragma unroll
            for (int j = 0; j < NFR; j++)
                wmma::store_matrix_sync(
                    Cf + (size_t)(m0 + wm * 32 + i * 16) * ldc + n0 + wn * WN + j * 16,
                    acc[i][j], ldc, wmma::mem_row_major);
        return;
    }

    constexpr int LDC_S = BN + 4;
    float* Cs = (float*)smem;
#pragma unroll
    for (int i = 0; i < 2; i++)
#pragma unroll
        for (int j = 0; j < NFR; j++)
            wmma::store_matrix_sync(Cs + (wm * 32 + i * 16) * LDC_S + wn * WN + j * 16,
                                    acc[i][j], LDC_S, wmma::mem_row_major);
    __syncthreads();

#pragma unroll
    for (int i = 0; i < BM * BN / 4 / 256; i++) {
        int f4  = t + i * 256;
        int row = f4 / (BN / 4);
        int c4  = (f4 % (BN / 4)) * 4;
        float4 v = *(const float4*)(Cs + row * LDC_S + c4);
        int col = n0 + c4;
        if (EPI >= 1) {
            float4 bv = *(const float4*)(bias + col);
            v.x += bv.x; v.y += bv.y; v.z += bv.z; v.w += bv.w;
        }
        if (EPI == 2) {
            float* p = &v.x;
#pragma unroll
            for (int e = 0; e < 4; e++) {
                float u = p[e];
                p[e] = 0.5f * u * (1.f + tanhf(0.7978845608f * (u + 0.044715f * u * u * u)));
            }
        }
        if (EPI == 3) {
            float4 rv = *(const float4*)(res + (size_t)(m0 + row) * ldc + col);
            v.x += rv.x; v.y += rv.y; v.z += rv.z; v.w += rv.w;
        }
        if (OUTH) {
            __half2 h01 = __floats2half2_rn(v.x, v.y);
            __half2 h23 = __floats2half2_rn(v.z, v.w);
            __half2* dst = (__half2*)(Ch + (size_t)(m0 + row) * ldc + col);
            dst[0] = h01; dst[1] = h23;
        } else {
            *(float4*)(Cf + (size_t)(m0 + row) * ldc + col) = v;
        }
    }
}

// ---------------- host launch ----------------
extern "C" void kernel_launch(void* const* d_in, const int* in_sizes, int n_in,
                              void* d_out, int out_size) {
    const float* x      = (const float*)d_in[0];
    const float* r      = (const float*)d_in[1];
    const float* ln1_g  = (const float*)d_in[2];
    const float* ln1_b  = (const float*)d_in[3];
    const float* qkv_w  = (const float*)d_in[4];
    const float* qkv_b  = (const float*)d_in[5];
    const float* conv_w = (const float*)d_in[6];
    const float* conv_b = (const float*)d_in[7];
    const float* proj_w = (const float*)d_in[8];
    const float* proj_b = (const float*)d_in[9];
    const float* ln2_g  = (const float*)d_in[10];
    const float* ln2_b  = (const float*)d_in[11];
    const float* fc1_w  = (const float*)d_in[12];
    const float* fc1_b  = (const float*)d_in[13];
    const float* fc2_w  = (const float*)d_in[14];
    const float* fc2_b  = (const float*)d_in[15];

    float* out    = (float*)d_out;
    float* out_x  = out;
    float* out_am = out + (size_t)ROWS * DIMC;
    float* out_un = out_am + (size_t)BC * HEADSC * NN;

    __half *h_, *qkvh_, *qk_, *attn_, *av_, *h2_, *fc1_, *wqkv_, *wpro_, *wfc1_, *wfc2_;
    float  *x1_, *fc2p_;
    cudaGetSymbolAddress((void**)&h_,    g_h);
    cudaGetSymbolAddress((void**)&qkvh_, g_qkvh);
    cudaGetSymbolAddress((void**)&qk_,   g_qk);
    cudaGetSymbolAddress((void**)&attn_, g_attn);
    cudaGetSymbolAddress((void**)&av_,   g_av);
    cudaGetSymbolAddress((void**)&x1_,   g_x1);
    cudaGetSymbolAddress((void**)&h2_,   g_h2);
    cudaGetSymbolAddress((void**)&fc1_,  g_fc1);
    cudaGetSymbolAddress((void**)&fc2p_, g_fc2p);
    cudaGetSymbolAddress((void**)&wqkv_, g_wqkv);
    cudaGetSymbolAddress((void**)&wpro_, g_wpro);
    cudaGetSymbolAddress((void**)&wfc1_, g_wfc1);
    cudaGetSymbolAddress((void**)&wfc2_, g_wfc2);

    // smem sizes (bytes)
    const int SM_NT128_64 = 2 * (128 * 72 + 128 * 72) * 2;    // 73728
    const int SM_QK_32    = 128 * (128 + 4) * 4;              // 67584
    const int SM_AV_64    = 2 * (128 * 72 + 64 * 72) * 2;     // 55296
    const int SM_MID      = (HEADSC * 256 * 4 + HEADSC * HEADSC + HEADSC
                             + 8 * HEADSC + HEADSC) * 4;      // 50208

    auto setsm = [](const void* f, int bytes) {
        cudaFuncSetAttribute(f, cudaFuncAttributeMaxDynamicSharedMemorySize, bytes);
        cudaFuncSetAttribute(f, cudaFuncAttributePreferredSharedMemoryCarveout, 100);
    };
    setsm((const void*)gemm_h<64,128,0,1,1>, SM_NT128_64);
    setsm((const void*)gemm_h<32,128,0,0,1>, SM_QK_32);
    setsm((const void*)gemm_h<64,64,1,0,1>,  SM_AV_64);
    setsm((const void*)gemm_h<64,128,0,3,0>, SM_NT128_64);
    setsm((const void*)gemm_h<64,128,0,2,1>, SM_NT128_64);
    setsm((const void*)gemm_h<64,128,0,0,0>, SM_NT128_64);
    setsm((const void*)mid_kernel,           SM_MID);

    // 0. weight conversion (single launch)
    {
        int total4 = (W0 + W1 + W2 + W3) / 4;
        f2h_all<<<(total4 + 255) / 256, 256>>>(qkv_w, proj_w, fc1_w, fc2_w,
                                               wqkv_, wpro_, wfc1_, wfc2_);
    }

    // 1. ln1
    ln_kernel<<<ROWS, 256>>>(x, ln1_g, ln1_b, h_);

    // 2. qkv = h @ qkv_w^T + qkv_b -> half (BK=64)
    gemm_h<64,128,0,1,1><<<dim3(3 * DIMC / 128, ROWS / 128, 1), 256, SM_NT128_64>>>(
        h_, wqkv_, qkvh_, qkv_b, nullptr,
        DIMC, DIMC, DIMC, 3 * DIMC,
        0, 0, 0, 0, 0, 0, 1);

    // 3. qk = Q @ K^T -> half raw scores (BK=32)
    gemm_h<32,128,0,0,1><<<dim3(NC / 128, NC / 128, BC * HEADSC), 256, SM_QK_32>>>(
        qkvh_, qkvh_ + DIMC, qk_, nullptr, nullptr,
        HDC, 3 * DIMC, 3 * DIMC, NC,
        (long)NC * 3 * DIMC, HDC,
        (long)NC * 3 * DIMC, HDC,
        (long)HEADSC * NN, (long)NN,
        HEADSC);

    // 4. fused middle v2 (no max pass, smem-cached exps)
    mid_kernel<<<BC * NC, 256, SM_MID>>>(qk_, r, conv_w, conv_b, out_am, out_un, attn_);

    // 5. av = attn @ V -> half (BK=64)
    gemm_h<64,64,1,0,1><<<dim3(1, NC / 128, BC * HEADSC), 256, SM_AV_64>>>(
        attn_, qkvh_ + 2 * DIMC, av_, nullptr, nullptr,
        NC, NC, 3 * DIMC, DIMC,
        (long)HEADSC * NN, (long)NN,
        (long)NC * 3 * DIMC, HDC,
        (long)NC * DIMC, HDC,
        HEADSC);

    // 6. x1 = x + av @ proj_w^T + proj_b -> fp32 (BK=64)
    gemm_h<64,128,0,3,0><<<dim3(DIMC / 128, ROWS / 128, 1), 256, SM_NT128_64>>>(
        av_, wpro_, x1_, proj_b, x,
        DIMC, DIMC, DIMC, DIMC,
        0, 0, 0, 0, 0, 0, 1);

    // 7. ln2
    ln_kernel<<<ROWS, 256>>>(x1_, ln2_g, ln2_b, h2_);

    // 8. fc1 = gelu(h2 @ fc1_w^T + fc1_b) -> half (BK=64)
    gemm_h<64,128,0,2,1><<<dim3(MLPC / 128, ROWS / 128, 1), 256, SM_NT128_64>>>(
        h2_, wfc1_, fc1_, fc1_b, nullptr,
        DIMC, DIMC, DIMC, MLPC,
        0, 0, 0, 0, 0, 0, 1);

    // 9a. fc2 split-K partials
    gemm_h<64,128,0,0,0><<<dim3(DIMC / 128, ROWS / 128, NSPLIT), 256, SM_NT128_64>>>(
        fc1_, wfc2_, fc2p_, nullptr, nullptr,
        MLPC / NSPLIT, MLPC, MLPC, DIMC,
        (long)(MLPC / NSPLIT), 0,
        (long)(MLPC / NSPLIT), 0,
        (long)ROWS * DIMC, 0,
        1);

    // 9b. out_x = x1 + fc2_b + sum partials
    fc2_reduce_kernel<<<ROWS * DIMC / 4 / 256, 256>>>(fc2p_, x1_, fc2_b, out_x);
}

// round 15
// speedup vs baseline: 1.0219x; 1.0219x over previous
#include <cuda_runtime.h>
#include <cuda_fp16.h>
#include <mma.h>
#include <math.h>

using namespace nvcuda;

#define DIMC   768
#define HEADSC 12
#define HDC    64
#define BC     2
#define NC     1024
#define MLPC   3072
#define ROWS   (BC * NC)
#define NN     (NC * NC)
#define SCALEC 0.125f
#define NSPLIT 4
#define NSPLITP 2

// ---------------- scratch ----------------
__device__ __half g_h   [ROWS * DIMC];
__device__ __half g_qkvh[ROWS * 3 * DIMC];
__device__ __half g_qk  [(size_t)BC * HEADSC * NN];
__device__ __half g_attn[(size_t)BC * HEADSC * NN];
__device__ __half g_av  [ROWS * DIMC];
__device__ float  g_x1  [ROWS * DIMC];
__device__ __half g_h2  [ROWS * DIMC];
__device__ __half g_fc1 [ROWS * MLPC];
__device__ float  g_fc2p[NSPLIT * ROWS * DIMC];
__device__ float  g_prjp[NSPLITP * ROWS * DIMC];
__device__ __half g_wqkv[3 * DIMC * DIMC];
__device__ __half g_wpro[DIMC * DIMC];
__device__ __half g_wfc1[MLPC * DIMC];
__device__ __half g_wfc2[DIMC * MLPC];

// ---------------- fused weight fp32->fp16 ----------------
#define W0 (3 * DIMC * DIMC)
#define W1 (DIMC * DIMC)
#define W2 (MLPC * DIMC)
#define W3 (DIMC * MLPC)
__global__ void f2h_all(const float* __restrict__ a, const float* __restrict__ b,
                        const float* __restrict__ c, const float* __restrict__ d,
                        __half* __restrict__ oa, __half* __restrict__ ob,
                        __half* __restrict__ oc, __half* __restrict__ od) {
    size_t i4 = (size_t)blockIdx.x * 256 + threadIdx.x;
    size_t i  = i4 * 4;
    const float* src; __half* dst; size_t off;
    if (i < W0)                { src = a; dst = oa; off = i; }
    else if (i < W0 + W1)      { src = b; dst = ob; off = i - W0; }
    else if (i < W0 + W1 + W2) { src = c; dst = oc; off = i - W0 - W1; }
    else if (i < W0 + W1 + W2 + W3) { src = d; dst = od; off = i - W0 - W1 - W2; }
    else return;
    float4 v = *(const float4*)(src + off);
    __half2* o2 = (__half2*)(dst + off);
    o2[0] = __floats2half2_rn(v.x, v.y);
    o2[1] = __floats2half2_rn(v.z, v.w);
}

// ---------------- layernorm (half out) ----------------
__global__ void ln_kernel(const float* __restrict__ x, const float* __restrict__ g,
                          const float* __restrict__ b, __half* __restrict__ y) {
    int row = blockIdx.x;
    const float* xr = x + (size_t)row * DIMC;
    __half*      yr = y + (size_t)row * DIMC;
    float v[3];
    float s = 0.f, s2 = 0.f;
#pragma unroll
    for (int i = 0; i < 3; i++) {
        v[i] = xr[threadIdx.x + 256 * i];
        s += v[i]; s2 += v[i] * v[i];
    }
    __shared__ float sh[16];
#pragma unroll
    for (int o = 16; o; o >>= 1) {
        s  += __shfl_xor_sync(~0u, s,  o);
        s2 += __shfl_xor_sync(~0u, s2, o);
    }
    int w = threadIdx.x >> 5;
    if ((threadIdx.x & 31) == 0) { sh[w] = s; sh[8 + w] = s2; }
    __syncthreads();
    if (threadIdx.x < 32) {
        s  = threadIdx.x < 8 ? sh[threadIdx.x]     : 0.f;
        s2 = threadIdx.x < 8 ? sh[8 + threadIdx.x] : 0.f;
#pragma unroll
        for (int o = 4; o; o >>= 1) {
            s  += __shfl_xor_sync(~0u, s,  o);
            s2 += __shfl_xor_sync(~0u, s2, o);
        }
        if (threadIdx.x == 0) { sh[0] = s; sh[1] = s2; }
    }
    __syncthreads();
    float mean = sh[0] * (1.f / DIMC);
    float var  = sh[1] * (1.f / DIMC) - mean * mean;
    float rstd = rsqrtf(var + 1e-5f);
#pragma unroll
    for (int i = 0; i < 3; i++) {
        int c = threadIdx.x + 256 * i;
        yr[c] = __float2half_rn((v[i] - mean) * rstd * g[c] + b[c]);
    }
}

// ------ fused middle: R13-exact (256 threads x 4 m-positions) ------
__global__ __launch_bounds__(256)
void mid_kernel(const __half* __restrict__ qk, const float* __restrict__ r,
                const float* __restrict__ cw, const float* __restrict__ cb,
                float* __restrict__ am, float* __restrict__ unc,
                __half* __restrict__ attn) {
    __shared__ float scw[HEADSC * HEADSC];
    __shared__ float scb[HEADSC];
    __shared__ float red[8 * HEADSC];
    __shared__ float fmx[HEADSC];
    __shared__ float fnv[HEADSC];

    int t  = threadIdx.x;
    int bn = blockIdx.x;
    int b  = bn >> 10, n = bn & 1023;
    if (t < HEADSC * HEADSC) scw[t] = cw[t];
    if (t < HEADSC)          scb[t] = cb[t];

    size_t base = (((size_t)b * HEADSC) << 20) + ((size_t)n << 10) + t * 4;

    float4 sv[HEADSC];
#pragma unroll
    for (int h = 0; h < HEADSC; h++) {
        const __half2* qp = (const __half2*)(qk + base + ((size_t)h << 20));
        __half2 q0 = qp[0], q1 = qp[1];
        float2 f0 = __half22float2(q0), f1 = __half22float2(q1);
        sv[h] = make_float4(f0.x, f0.y, f1.x, f1.y);
    }

#pragma unroll
    for (int h = 0; h < HEADSC; h++) {
        float m = fmaxf(fmaxf(sv[h].x, sv[h].y), fmaxf(sv[h].z, sv[h].w));
#pragma unroll
        for (int o = 16; o; o >>= 1) m = fmaxf(m, __shfl_xor_sync(~0u, m, o));
        if ((t & 31) == 0) red[(t >> 5) * HEADSC + h] = m;
    }
    __syncthreads();
    if (t < HEADSC) {
        float m = red[t];
#pragma unroll
        for (int ww = 1; ww < 8; ww++) m = fmaxf(m, red[ww * HEADSC + t]);
        fmx[t] = m * SCALEC;
    }
    __syncthreads();

#pragma unroll
    for (int h = 0; h < HEADSC; h++) {
        float mm = fmx[h];
        float s = __expf(sv[h].x * SCALEC - mm) + __expf(sv[h].y * SCALEC - mm)
                + __expf(sv[h].z * SCALEC - mm) + __expf(sv[h].w * SCALEC - mm);
#pragma unroll
        for (int o = 16; o; o >>= 1) s += __shfl_xor_sync(~0u, s, o);
        if ((t & 31) == 0) red[(t >> 5) * HEADSC + h] = s;
    }
    __syncthreads();
    if (t < HEADSC) {
        float s = 0.f;
#pragma unroll
        for (int ww = 0; ww < 8; ww++) s += red[ww * HEADSC + t];
        fnv[t] = 1.f / s;
    }
    __syncthreads();

#pragma unroll
    for (int g = 0; g < HEADSC; g++) {
        float ax = scb[g], ay = scb[g], az = scb[g], aw = scb[g];
#pragma unroll
        for (int h = 0; h < HEADSC; h++) {
            float wv = scw[g * HEADSC + h];
            ax += wv * sv[h].x; ay += wv * sv[h].y;
            az += wv * sv[h].z; aw += wv * sv[h].w;
        }
        float4 u;
        u.x = 1.f / (1.f + __expf(-ax));
        u.y = 1.f / (1.f + __expf(-ay));
        u.z = 1.f / (1.f + __expf(-az));
        u.w = 1.f / (1.f + __expf(-aw));
        float mm = fmx[g], iv = fnv[g];
        float4 p;
        p.x = __expf(sv[g].x * SCALEC - mm) * iv;
        p.y = __expf(sv[g].y * SCALEC - mm) * iv;
        p.z = __expf(sv[g].z * SCALEC - mm) * iv;
        p.w = __expf(sv[g].w * SCALEC - mm) * iv;
        size_t o = base + ((size_t)g << 20);
        float4 rv = *(const float4*)(r + o);
        *(float4*)(am + o)  = p;
        *(float4*)(unc + o) = u;
        __half2* at = (__half2*)(attn + o);
        at[0] = __floats2half2_rn(p.x + u.x * rv.x, p.y + u.y * rv.y);
        at[1] = __floats2half2_rn(p.z + u.z * rv.z, p.w + u.w * rv.w);
    }
}

// ------ split-K reduce: out = res + bias + sum of NS partials ------
template<int NS>
__global__ void splitk_reduce_kernel(const float* __restrict__ part,
                                     const float* __restrict__ res,
                                     const float* __restrict__ bias,
                                     float* __restrict__ out) {
    size_t i = ((size_t)blockIdx.x * 256 + threadIdx.x) * 4;
    int col = (int)(i % DIMC);
    float4 v  = *(const float4*)(res + i);
    float4 bv = *(const float4*)(bias + col);
    v.x += bv.x; v.y += bv.y; v.z += bv.z; v.w += bv.w;
#pragma unroll
    for (int s = 0; s < NS; s++) {
        float4 p = *(const float4*)(part + (size_t)s * ROWS * DIMC + i);
        v.x += p.x; v.y += p.y; v.z += p.z; v.w += p.w;
    }
    *(float4*)(out + i) = v;
}

// ---------------- fp16 tensor-core GEMM (2-stage cp.async, templated BK) ----------------
__device__ __forceinline__ void cpa16h(__half* dst, const __half* src) {
    unsigned s = (unsigned)__cvta_generic_to_shared(dst);
    asm volatile("cp.async.cg.shared.global [%0], [%1], 16;" :: "r"(s), "l"(src));
}

template<int BK, int BN, int BLAY, int EPI, int OUTH>
__global__ __launch_bounds__(256)
void gemm_h(const __half* __restrict__ A, const __half* __restrict__ B,
            void* __restrict__ Cv, const float* __restrict__ bias,
            const float* __restrict__ res,
            int K, int lda, int ldb, int ldc,
            long sAb, long sAh, long sBb, long sBh, long sCb, long sCh,
            int Hdiv) {
    constexpr int BM  = 128;
    constexpr int LDS = BK + 8;
    constexpr int WN  = BN / 2;
    constexpr int NFR = WN / 16;
    constexpr int ASZ = BM * LDS;
    constexpr int LDB_S = (BLAY == 0) ? LDS : (BN + 8);
    constexpr int BSZ = (BLAY == 0) ? BN * LDS : BK * LDB_S;
    constexpr int CPR = BK / 8;

    extern __shared__ __half smem[];
    __half* As[2] = { smem,       smem + ASZ + BSZ };
    __half* Bs[2] = { smem + ASZ, smem + 2 * ASZ + BSZ };

    int z  = blockIdx.z;
    int zb = z / Hdiv, zh = z % Hdiv;
    A += zb * sAb + zh * sAh;
    B += zb * sBb + zh * sBh;
    size_t coff = (size_t)zb * sCb + (size_t)zh * sCh;
    float*  Cf = (float*)Cv + coff;
    __half* Ch = (__half*)Cv + coff;
    if (EPI == 3) res += coff;

    int m0 = blockIdx.y * BM, n0 = blockIdx.x * BN;
    int t   = threadIdx.x;
    int wid = t >> 5;
    int wm  = wid & 3;
    int wn  = wid >> 2;

    wmma::fragment<wmma::accumulator, 16, 16, 16, float> acc[2][NFR];
#pragma unroll
    for (int i = 0; i < 2; i++)
#pragma unroll
        for (int j = 0; j < NFR; j++) wmma::fill_fragment(acc[i][j], 0.f);

    const int stages = K / BK;

    auto load_tiles = [&](int k0, int st) {
#pragma unroll
        for (int i = 0; i < BM * BK / 8 / 256; i++) {
            int f   = t + i * 256;
            int row = f / CPR;
            int c8  = (f % CPR) * 8;
            cpa16h(As[st] + row * LDS + c8,
                   A + (size_t)(m0 + row) * lda + k0 + c8);
        }
        if (BLAY == 0) {
#pragma unroll
            for (int i = 0; i < BN * BK / 8 / 256; i++) {
                int f   = t + i * 256;
                int row = f / CPR;
                int c8  = (f % CPR) * 8;
                cpa16h(Bs[st] + row * LDS + c8,
                       B + (size_t)(n0 + row) * ldb + k0 + c8);
            }
        } else {
#pragma unroll
            for (int i = 0; i < BK * BN / 8 / 256; i++) {
                int f   = t + i * 256;
                int row = f / (BN / 8);
                int c8  = (f % (BN / 8)) * 8;
                cpa16h(Bs[st] + row * LDB_S + c8,
                       B + (size_t)(k0 + row) * ldb + n0 + c8);
            }
        }
        asm volatile("cp.async.commit_group;" ::: "memory");
    };

    load_tiles(0, 0);

    for (int it = 0; it < stages; ++it) {
        int cur = it & 1;
        if (it + 1 < stages) {
            load_tiles((it + 1) * BK, cur ^ 1);
            asm volatile("cp.async.wait_group 1;" ::: "memory");
        } else {
            asm volatile("cp.async.wait_group 0;" ::: "memory");
        }
        __syncthreads();

        const __half* as = As[cur];
        const __half* bs = Bs[cur];
#pragma unroll
        for (int kk = 0; kk < BK; kk += 16) {
            wmma::fragment<wmma::matrix_a, 16, 16, 16, __half, wmma::row_major> af[2];
#pragma unroll
            for (int i = 0; i < 2; i++)
                wmma::load_matrix_sync(af[i], as + (wm * 32 + i * 16) * LDS + kk, LDS);
            if (BLAY == 0) {
#pragma unroll
                for (int j = 0; j < NFR; j++) {
                    wmma::fragment<wmma::matrix_b, 16, 16, 16, __half, wmma::col_major> bf;
                    wmma::load_matrix_sync(bf, bs + (wn * WN + j * 16) * LDS + kk, LDS);
#pragma unroll
                    for (int i = 0; i < 2; i++)
                        wmma::mma_sync(acc[i][j], af[i], bf, acc[i][j]);
                }
            } else {
#pragma unroll
                for (int j = 0; j < NFR; j++) {
                    wmma::fragment<wmma::matrix_b, 16, 16, 16, __half, wmma::row_major> bf;
                    wmma::load_matrix_sync(bf, bs + kk * LDB_S + wn * WN + j * 16, LDB_S);
#pragma unroll
                    for (int i = 0; i < 2; i++)
                        wmma::mma_sync(acc[i][j], af[i], bf, acc[i][j]);
                }
            }
        }
        __syncthreads();
    }

    if (EPI == 0 && OUTH == 0) {
#pragma unroll
        for (int i = 0; i < 2; i++)
#pragma unroll
            for (int j = 0; j < NFR; j++)
                wmma::store_matrix_sync(
                    Cf + (size_t)(m0 + wm * 32 + i * 16) * ldc + n0 + wn * WN + j * 16,
                    acc[i][j], ldc, wmma::mem_row_major);
        return;
    }

    constexpr int LDC_S = BN + 4;
    float* Cs = (float*)smem;
#pragma unroll
    for (int i = 0; i < 2; i++)
#pragma unroll
        for (int j = 0; j < NFR; j++)
            wmma::store_matrix_sync(Cs + (wm * 32 + i * 16) * LDC_S + wn * WN + j * 16,
                                    acc[i][j], LDC_S, wmma::mem_row_major);
    __syncthreads();

#pragma unroll
    for (int i = 0; i < BM * BN / 4 / 256; i++) {
        int f4  = t + i * 256;
        int row = f4 / (BN / 4);
        int c4  = (f4 % (BN / 4)) * 4;
        float4 v = *(const float4*)(Cs + row * LDC_S + c4);
        int col = n0 + c4;
        if (EPI >= 1) {
            float4 bv = *(const float4*)(bias + col);
            v.x += bv.x; v.y += bv.y; v.z += bv.z; v.w += bv.w;
        }
        if (EPI == 2) {
            float* p = &v.x;
#pragma unroll
            for (int e = 0; e < 4; e++) {
                float u = p[e];
                p[e] = 0.5f * u * (1.f + tanhf(0.7978845608f * (u + 0.044715f * u * u * u)));
            }
        }
        if (EPI == 3) {
            float4 rv = *(const float4*)(res + (size_t)(m0 + row) * ldc + col);
            v.x += rv.x; v.y += rv.y; v.z += rv.z; v.w += rv.w;
        }
        if (OUTH) {
            __half2 h01 = __floats2half2_rn(v.x, v.y);
            __half2 h23 = __floats2half2_rn(v.z, v.w);
            __half2* dst = (__half2*)(Ch + (size_t)(m0 + row) * ldc + col);
            dst[0] = h01; dst[1] = h23;
        } else {
            *(float4*)(Cf + (size_t)(m0 + row) * ldc + col) = v;
        }
    }
}

// ---------------- host launch ----------------
extern "C" void kernel_launch(void* const* d_in, const int* in_sizes, int n_in,
                              void* d_out, int out_size) {
    const float* x      = (const float*)d_in[0];
    const float* r      = (const float*)d_in[1];
    const float* ln1_g  = (const float*)d_in[2];
    const float* ln1_b  = (const float*)d_in[3];
    const float* qkv_w  = (const float*)d_in[4];
    const float* qkv_b  = (const float*)d_in[5];
    const float* conv_w = (const float*)d_in[6];
    const float* conv_b = (const float*)d_in[7];
    const float* proj_w = (const float*)d_in[8];
    const float* proj_b = (const float*)d_in[9];
    const float* ln2_g  = (const float*)d_in[10];
    const float* ln2_b  = (const float*)d_in[11];
    const float* fc1_w  = (const float*)d_in[12];
    const float* fc1_b  = (const float*)d_in[13];
    const float* fc2_w  = (const float*)d_in[14];
    const float* fc2_b  = (const float*)d_in[15];

    float* out    = (float*)d_out;
    float* out_x  = out;
    float* out_am = out + (size_t)ROWS * DIMC;
    float* out_un = out_am + (size_t)BC * HEADSC * NN;

    __half *h_, *qkvh_, *qk_, *attn_, *av_, *h2_, *fc1_, *wqkv_, *wpro_, *wfc1_, *wfc2_;
    float  *x1_, *fc2p_, *prjp_;
    cudaGetSymbolAddress((void**)&h_,    g_h);
    cudaGetSymbolAddress((void**)&qkvh_, g_qkvh);
    cudaGetSymbolAddress((void**)&qk_,   g_qk);
    cudaGetSymbolAddress((void**)&attn_, g_attn);
    cudaGetSymbolAddress((void**)&av_,   g_av);
    cudaGetSymbolAddress((void**)&x1_,   g_x1);
    cudaGetSymbolAddress((void**)&h2_,   g_h2);
    cudaGetSymbolAddress((void**)&fc1_,  g_fc1);
    cudaGetSymbolAddress((void**)&fc2p_, g_fc2p);
    cudaGetSymbolAddress((void**)&prjp_, g_prjp);
    cudaGetSymbolAddress((void**)&wqkv_, g_wqkv);
    cudaGetSymbolAddress((void**)&wpro_, g_wpro);
    cudaGetSymbolAddress((void**)&wfc1_, g_wfc1);
    cudaGetSymbolAddress((void**)&wfc2_, g_wfc2);

    // smem sizes (bytes)
    const int SM_NT128_64 = 2 * (128 * 72 + 128 * 72) * 2;    // 73728
    const int SM_QK_32    = 128 * (128 + 4) * 4;              // 67584
    const int SM_AV_64    = 2 * (128 * 72 + 64 * 72) * 2;     // 55296

    auto setsm = [](const void* f, int bytes) {
        cudaFuncSetAttribute(f, cudaFuncAttributeMaxDynamicSharedMemorySize, bytes);
        cudaFuncSetAttribute(f, cudaFuncAttributePreferredSharedMemoryCarveout, 100);
    };
    setsm((const void*)gemm_h<64,128,0,1,1>, SM_NT128_64);
    setsm((const void*)gemm_h<32,128,0,0,1>, SM_QK_32);
    setsm((const void*)gemm_h<64,64,1,0,1>,  SM_AV_64);
    setsm((const void*)gemm_h<64,128,0,2,1>, SM_NT128_64);
    setsm((const void*)gemm_h<64,128,0,0,0>, SM_NT128_64);

    // 0. weight conversion (single launch)
    {
        int total4 = (W0 + W1 + W2 + W3) / 4;
        f2h_all<<<(total4 + 255) / 256, 256>>>(qkv_w, proj_w, fc1_w, fc2_w,
                                               wqkv_, wpro_, wfc1_, wfc2_);
    }

    // 1. ln1
    ln_kernel<<<ROWS, 256>>>(x, ln1_g, ln1_b, h_);

    // 2. qkv = h @ qkv_w^T + qkv_b -> half (BK=64)
    gemm_h<64,128,0,1,1><<<dim3(3 * DIMC / 128, ROWS / 128, 1), 256, SM_NT128_64>>>(
        h_, wqkv_, qkvh_, qkv_b, nullptr,
        DIMC, DIMC, DIMC, 3 * DIMC,
        0, 0, 0, 0, 0, 0, 1);

    // 3. qk = Q @ K^T -> half raw scores (BK=32)
    gemm_h<32,128,0,0,1><<<dim3(NC / 128, NC / 128, BC * HEADSC), 256, SM_QK_32>>>(
        qkvh_, qkvh_ + DIMC, qk_, nullptr, nullptr,
        HDC, 3 * DIMC, 3 * DIMC, NC,
        (long)NC * 3 * DIMC, HDC,
        (long)NC * 3 * DIMC, HDC,
        (long)HEADSC * NN, (long)NN,
        HEADSC);

    // 4. fused middle (R13-exact)
    mid_kernel<<<BC * NC, 256>>>(qk_, r, conv_w, conv_b, out_am, out_un, attn_);

    // 5. av = attn @ V -> half (BK=64)
    gemm_h<64,64,1,0,1><<<dim3(1, NC / 128, BC * HEADSC), 256, SM_AV_64>>>(
        attn_, qkvh_ + 2 * DIMC, av_, nullptr, nullptr,
        NC, NC, 3 * DIMC, DIMC,
        (long)HEADSC * NN, (long)NN,
        (long)NC * 3 * DIMC, HDC,
        (long)NC * DIMC, HDC,
        HEADSC);

    // 6a. proj split-K partials: part[s] = av[:, s*384:] @ proj_w[:, s*384:]^T
    gemm_h<64,128,0,0,0><<<dim3(DIMC / 128, ROWS / 128, NSPLITP), 256, SM_NT128_64>>>(
        av_, wpro_, prjp_, nullptr, nullptr,
        DIMC / NSPLITP, DIMC, DIMC, DIMC,
        (long)(DIMC / NSPLITP), 0,
        (long)(DIMC / NSPLITP), 0,
        (long)ROWS * DIMC, 0,
        1);

    // 6b. x1 = x + proj_b + sum partials
    splitk_reduce_kernel<NSPLITP><<<ROWS * DIMC / 4 / 256, 256>>>(prjp_, x, proj_b, x1_);

    // 7. ln2
    ln_kernel<<<ROWS, 256>>>(x1_, ln2_g, ln2_b, h2_);

    // 8. fc1 = gelu(h2 @ fc1_w^T + fc1_b) -> half (BK=64)
    gemm_h<64,128,0,2,1><<<dim3(MLPC / 128, ROWS / 128, 1), 256, SM_NT128_64>>>(
        h2_, wfc1_, fc1_, fc1_b, nullptr,
        DIMC, DIMC, DIMC, MLPC,
        0, 0, 0, 0, 0, 0, 1);

    // 9a. fc2 split-K partials
    gemm_h<64,128,0,0,0><<<dim3(DIMC / 128, ROWS / 128, NSPLIT), 256, SM_NT128_64>>>(
        fc1_, wfc2_, fc2p_, nullptr, nullptr,
        MLPC / NSPLIT, MLPC, MLPC, DIMC,
        (long)(MLPC / NSPLIT), 0,
        (long)(MLPC / NSPLIT), 0,
        (long)ROWS * DIMC, 0,
        1);

    // 9b. out_x = x1 + fc2_b + sum partials
    splitk_reduce_kernel<NSPLIT><<<ROWS * DIMC / 4 / 256, 256>>>(fc2p_, x1_, fc2_b, out_x);
}

// round 16
// speedup vs baseline: 1.0338x; 1.0117x over previous
#include <cuda_runtime.h>
#include <cuda_fp16.h>
#include <mma.h>
#include <math.h>

using namespace nvcuda;

#define DIMC   768
#define HEADSC 12
#define HDC    64
#define BC     2
#define NC     1024
#define MLPC   3072
#define ROWS   (BC * NC)
#define NN     (NC * NC)
#define SCALEC 0.125f
#define NSPLIT 4

// ---------------- scratch ----------------
__device__ __half g_h   [ROWS * DIMC];
__device__ __half g_qkvh[ROWS * 3 * DIMC];
__device__ __half g_qk  [(size_t)BC * HEADSC * NN];
__device__ __half g_attn[(size_t)BC * HEADSC * NN];
__device__ __half g_av  [ROWS * DIMC];
__device__ float  g_x1  [ROWS * DIMC];
__device__ __half g_h2  [ROWS * DIMC];
__device__ __half g_fc1 [ROWS * MLPC];
__device__ float  g_fc2p[NSPLIT * ROWS * DIMC];
__device__ __half g_wqkv[3 * DIMC * DIMC];
__device__ __half g_wpro[DIMC * DIMC];
__device__ __half g_wfc1[MLPC * DIMC];
__device__ __half g_wfc2[DIMC * MLPC];

// ---------------- fused weight fp32->fp16 ----------------
#define W0 (3 * DIMC * DIMC)
#define W1 (DIMC * DIMC)
#define W2 (MLPC * DIMC)
#define W3 (DIMC * MLPC)
__global__ void f2h_all(const float* __restrict__ a, const float* __restrict__ b,
                        const float* __restrict__ c, const float* __restrict__ d,
                        __half* __restrict__ oa, __half* __restrict__ ob,
                        __half* __restrict__ oc, __half* __restrict__ od) {
    size_t i4 = (size_t)blockIdx.x * 256 + threadIdx.x;
    size_t i  = i4 * 4;
    const float* src; __half* dst; size_t off;
    if (i < W0)                { src = a; dst = oa; off = i; }
    else if (i < W0 + W1)      { src = b; dst = ob; off = i - W0; }
    else if (i < W0 + W1 + W2) { src = c; dst = oc; off = i - W0 - W1; }
    else if (i < W0 + W1 + W2 + W3) { src = d; dst = od; off = i - W0 - W1 - W2; }
    else return;
    float4 v = *(const float4*)(src + off);
    __half2* o2 = (__half2*)(dst + off);
    o2[0] = __floats2half2_rn(v.x, v.y);
    o2[1] = __floats2half2_rn(v.z, v.w);
}

// ---------------- layernorm (half out) ----------------
__global__ void ln_kernel(const float* __restrict__ x, const float* __restrict__ g,
                          const float* __restrict__ b, __half* __restrict__ y) {
    int row = blockIdx.x;
    const float* xr = x + (size_t)row * DIMC;
    __half*      yr = y + (size_t)row * DIMC;
    float v[3];
    float s = 0.f, s2 = 0.f;
#pragma unroll
    for (int i = 0; i < 3; i++) {
        v[i] = xr[threadIdx.x + 256 * i];
        s += v[i]; s2 += v[i] * v[i];
    }
    __shared__ float sh[16];
#pragma unroll
    for (int o = 16; o; o >>= 1) {
        s  += __shfl_xor_sync(~0u, s,  o);
        s2 += __shfl_xor_sync(~0u, s2, o);
    }
    int w = threadIdx.x >> 5;
    if ((threadIdx.x & 31) == 0) { sh[w] = s; sh[8 + w] = s2; }
    __syncthreads();
    if (threadIdx.x < 32) {
        s  = threadIdx.x < 8 ? sh[threadIdx.x]     : 0.f;
        s2 = threadIdx.x < 8 ? sh[8 + threadIdx.x] : 0.f;
#pragma unroll
        for (int o = 4; o; o >>= 1) {
            s  += __shfl_xor_sync(~0u, s,  o);
            s2 += __shfl_xor_sync(~0u, s2, o);
        }
        if (threadIdx.x == 0) { sh[0] = s; sh[1] = s2; }
    }
    __syncthreads();
    float mean = sh[0] * (1.f / DIMC);
    float var  = sh[1] * (1.f / DIMC) - mean * mean;
    float rstd = rsqrtf(var + 1e-5f);
#pragma unroll
    for (int i = 0; i < 3; i++) {
        int c = threadIdx.x + 256 * i;
        yr[c] = __float2half_rn((v[i] - mean) * rstd * g[c] + b[c]);
    }
}

// ------ fused middle (R13 + streaming stores for am/unc) ------
__global__ __launch_bounds__(256)
void mid_kernel(const __half* __restrict__ qk, const float* __restrict__ r,
                const float* __restrict__ cw, const float* __restrict__ cb,
                float* __restrict__ am, float* __restrict__ unc,
                __half* __restrict__ attn) {
    __shared__ float scw[HEADSC * HEADSC];
    __shared__ float scb[HEADSC];
    __shared__ float red[8 * HEADSC];
    __shared__ float fmx[HEADSC];
    __shared__ float fnv[HEADSC];

    int t  = threadIdx.x;
    int bn = blockIdx.x;
    int b  = bn >> 10, n = bn & 1023;
    if (t < HEADSC * HEADSC) scw[t] = cw[t];
    if (t < HEADSC)          scb[t] = cb[t];

    size_t base = (((size_t)b * HEADSC) << 20) + ((size_t)n << 10) + t * 4;

    float4 sv[HEADSC];
#pragma unroll
    for (int h = 0; h < HEADSC; h++) {
        const __half2* qp = (const __half2*)(qk + base + ((size_t)h << 20));
        __half2 q0 = qp[0], q1 = qp[1];
        float2 f0 = __half22float2(q0), f1 = __half22float2(q1);
        sv[h] = make_float4(f0.x, f0.y, f1.x, f1.y);
    }

#pragma unroll
    for (int h = 0; h < HEADSC; h++) {
        float m = fmaxf(fmaxf(sv[h].x, sv[h].y), fmaxf(sv[h].z, sv[h].w));
#pragma unroll
        for (int o = 16; o; o >>= 1) m = fmaxf(m, __shfl_xor_sync(~0u, m, o));
        if ((t & 31) == 0) red[(t >> 5) * HEADSC + h] = m;
    }
    __syncthreads();
    if (t < HEADSC) {
        float m = red[t];
#pragma unroll
        for (int ww = 1; ww < 8; ww++) m = fmaxf(m, red[ww * HEADSC + t]);
        fmx[t] = m * SCALEC;
    }
    __syncthreads();

#pragma unroll
    for (int h = 0; h < HEADSC; h++) {
        float mm = fmx[h];
        float s = __expf(sv[h].x * SCALEC - mm) + __expf(sv[h].y * SCALEC - mm)
                + __expf(sv[h].z * SCALEC - mm) + __expf(sv[h].w * SCALEC - mm);
#pragma unroll
        for (int o = 16; o; o >>= 1) s += __shfl_xor_sync(~0u, s, o);
        if ((t & 31) == 0) red[(t >> 5) * HEADSC + h] = s;
    }
    __syncthreads();
    if (t < HEADSC) {
        float s = 0.f;
#pragma unroll
        for (int ww = 0; ww < 8; ww++) s += red[ww * HEADSC + t];
        fnv[t] = 1.f / s;
    }
    __syncthreads();

#pragma unroll
    for (int g = 0; g < HEADSC; g++) {
        float ax = scb[g], ay = scb[g], az = scb[g], aw = scb[g];
#pragma unroll
        for (int h = 0; h < HEADSC; h++) {
            float wv = scw[g * HEADSC + h];
            ax += wv * sv[h].x; ay += wv * sv[h].y;
            az += wv * sv[h].z; aw += wv * sv[h].w;
        }
        float4 u;
        u.x = 1.f / (1.f + __expf(-ax));
        u.y = 1.f / (1.f + __expf(-ay));
        u.z = 1.f / (1.f + __expf(-az));
        u.w = 1.f / (1.f + __expf(-aw));
        float mm = fmx[g], iv = fnv[g];
        float4 p;
        p.x = __expf(sv[g].x * SCALEC - mm) * iv;
        p.y = __expf(sv[g].y * SCALEC - mm) * iv;
        p.z = __expf(sv[g].z * SCALEC - mm) * iv;
        p.w = __expf(sv[g].w * SCALEC - mm) * iv;
        size_t o = base + ((size_t)g << 20);
        float4 rv = *(const float4*)(r + o);
        __stwt((float4*)(am + o), p);          // streaming: never re-read
        __stwt((float4*)(unc + o), u);         // streaming: never re-read
        __half2* at = (__half2*)(attn + o);
        at[0] = __floats2half2_rn(p.x + u.x * rv.x, p.y + u.y * rv.y);
        at[1] = __floats2half2_rn(p.z + u.z * rv.z, p.w + u.w * rv.w);
    }
}

// ------ split-K reduce: out = res + bias + sum of NS partials ------
template<int NS>
__global__ void splitk_reduce_kernel(const float* __restrict__ part,
                                     const float* __restrict__ res,
                                     const float* __restrict__ bias,
                                     float* __restrict__ out) {
    size_t i = ((size_t)blockIdx.x * 256 + threadIdx.x) * 4;
    int col = (int)(i % DIMC);
    float4 v  = *(const float4*)(res + i);
    float4 bv = *(const float4*)(bias + col);
    v.x += bv.x; v.y += bv.y; v.z += bv.z; v.w += bv.w;
#pragma unroll
    for (int s = 0; s < NS; s++) {
        float4 p = *(const float4*)(part + (size_t)s * ROWS * DIMC + i);
        v.x += p.x; v.y += p.y; v.z += p.z; v.w += p.w;
    }
    *(float4*)(out + i) = v;
}

// ---------------- fp16 tensor-core GEMM (2-stage cp.async, templated BK) ----------------
__device__ __forceinline__ void cpa16h(__half* dst, const __half* src) {
    unsigned s = (unsigned)__cvta_generic_to_shared(dst);
    asm volatile("cp.async.cg.shared.global [%0], [%1], 16;" :: "r"(s), "l"(src));
}

template<int BK, int BN, int BLAY, int EPI, int OUTH>
__global__ __launch_bounds__(256)
void gemm_h(const __half* __restrict__ A, const __half* __restrict__ B,
            void* __restrict__ Cv, const float* __restrict__ bias,
            const float* __restrict__ res,
            int K, int lda, int ldb, int ldc,
            long sAb, long sAh, long sBb, long sBh, long sCb, long sCh,
            int Hdiv) {
    constexpr int BM  = 128;
    constexpr int LDS = BK + 8;
    constexpr int WN  = BN / 2;
    constexpr int NFR = WN / 16;
    constexpr int ASZ = BM * LDS;
    constexpr int LDB_S = (BLAY == 0) ? LDS : (BN + 8);
    constexpr int BSZ = (BLAY == 0) ? BN * LDS : BK * LDB_S;
    constexpr int CPR = BK / 8;

    extern __shared__ __half smem[];
    __half* As[2] = { smem,       smem + ASZ + BSZ };
    __half* Bs[2] = { smem + ASZ, smem + 2 * ASZ + BSZ };

    int z  = blockIdx.z;
    int zb = z / Hdiv, zh = z % Hdiv;
    A += zb * sAb + zh * sAh;
    B += zb * sBb + zh * sBh;
    size_t coff = (size_t)zb * sCb + (size_t)zh * sCh;
    float*  Cf = (float*)Cv + coff;
    __half* Ch = (__half*)Cv + coff;
    if (EPI == 3) res += coff;

    int m0 = blockIdx.y * BM, n0 = blockIdx.x * BN;
    int t   = threadIdx.x;
    int wid = t >> 5;
    int wm  = wid & 3;
    int wn  = wid >> 2;

    wmma::fragment<wmma::accumulator, 16, 16, 16, float> acc[2][NFR];
#pragma unroll
    for (int i = 0; i < 2; i++)
#pragma unroll
        for (int j = 0; j < NFR; j++) wmma::fill_fragment(acc[i][j], 0.f);

    const int stages = K / BK;

    auto load_tiles = [&](int k0, int st) {
#pragma unroll
        for (int i = 0; i < BM * BK / 8 / 256; i++) {
            int f   = t + i * 256;
            int row = f / CPR;
            int c8  = (f % CPR) * 8;
            cpa16h(As[st] + row * LDS + c8,
                   A + (size_t)(m0 + row) * lda + k0 + c8);
        }
        if (BLAY == 0) {
#pragma unroll
            for (int i = 0; i < BN * BK / 8 / 256; i++) {
                int f   = t + i * 256;
                int row = f / CPR;
                int c8  = (f % CPR) * 8;
                cpa16h(Bs[st] + row * LDS + c8,
                       B + (size_t)(n0 + row) * ldb + k0 + c8);
            }
        } else {
#pragma unroll
            for (int i = 0; i < BK * BN / 8 / 256; i++) {
                int f   = t + i * 256;
                int row = f / (BN / 8);
                int c8  = (f % (BN / 8)) * 8;
                cpa16h(Bs[st] + row * LDB_S + c8,
                       B + (size_t)(k0 + row) * ldb + n0 + c8);
            }
        }
        asm volatile("cp.async.commit_group;" ::: "memory");
    };

    load_tiles(0, 0);

    for (int it = 0; it < stages; ++it) {
        int cur = it & 1;
        if (it + 1 < stages) {
            load_tiles((it + 1) * BK, cur ^ 1);
            asm volatile("cp.async.wait_group 1;" ::: "memory");
        } else {
            asm volatile("cp.async.wait_group 0;" ::: "memory");
        }
        __syncthreads();

        const __half* as = As[cur];
        const __half* bs = Bs[cur];
#pragma unroll
        for (int kk = 0; kk < BK; kk += 16) {
            wmma::fragment<wmma::matrix_a, 16, 16, 16, __half, wmma::row_major> af[2];
#pragma unroll
            for (int i = 0; i < 2; i++)
                wmma::load_matrix_sync(af[i], as + (wm * 32 + i * 16) * LDS + kk, LDS);
            if (BLAY == 0) {
#pragma unroll
                for (int j = 0; j < NFR; j++) {
                    wmma::fragment<wmma::matrix_b, 16, 16, 16, __half, wmma::col_major> bf;
                    wmma::load_matrix_sync(bf, bs + (wn * WN + j * 16) * LDS + kk, LDS);
#pragma unroll
                    for (int i = 0; i < 2; i++)
                        wmma::mma_sync(acc[i][j], af[i], bf, acc[i][j]);
                }
            } else {
#pragma unroll
                for (int j = 0; j < NFR; j++) {
                    wmma::fragment<wmma::matrix_b, 16, 16, 16, __half, wmma::row_major> bf;
                    wmma::load_matrix_sync(bf, bs + kk * LDB_S + wn * WN + j * 16, LDB_S);
#pragma unroll
                    for (int i = 0; i < 2; i++)
                        wmma::mma_sync(acc[i][j], af[i], bf, acc[i][j]);
                }
            }
        }
        __syncthreads();
    }

    if (EPI == 0 && OUTH == 0) {
#pragma unroll
        for (int i = 0; i < 2; i++)
#pragma unroll
            for (int j = 0; j < NFR; j++)
                wmma::store_matrix_sync(
                    Cf + (size_t)(m0 + wm * 32 + i * 16) * ldc + n0 + wn * WN + j * 16,
                    acc[i][j], ldc, wmma::mem_row_major);
        return;
    }

    constexpr int LDC_S = BN + 4;
    float* Cs = (float*)smem;
#pragma unroll
    for (int i = 0; i < 2; i++)
#pragma unroll
        for (int j = 0; j < NFR; j++)
            wmma::store_matrix_sync(Cs + (wm * 32 + i * 16) * LDC_S + wn * WN + j * 16,
                                    acc[i][j], LDC_S, wmma::mem_row_major);
    __syncthreads();

#pragma unroll
    for (int i = 0; i < BM * BN / 4 / 256; i++) {
        int f4  = t + i * 256;
        int row = f4 / (BN / 4);
        int c4  = (f4 % (BN / 4)) * 4;
        float4 v = *(const float4*)(Cs + row * LDC_S + c4);
        int col = n0 + c4;
        if (EPI >= 1) {
            float4 bv = *(const float4*)(bias + col);
            v.x += bv.x; v.y += bv.y; v.z += bv.z; v.w += bv.w;
        }
        if (EPI == 2) {
            float* p = &v.x;
#pragma unroll
            for (int e = 0; e < 4; e++) {
                float u = p[e];
                p[e] = 0.5f * u * (1.f + tanhf(0.7978845608f * (u + 0.044715f * u * u * u)));
            }
        }
        if (EPI == 3) {
            float4 rv = *(const float4*)(res + (size_t)(m0 + row) * ldc + col);
            v.x += rv.x; v.y += rv.y; v.z += rv.z; v.w += rv.w;
        }
        if (OUTH) {
            __half2 h01 = __floats2half2_rn(v.x, v.y);
            __half2 h23 = __floats2half2_rn(v.z, v.w);
            __half2* dst = (__half2*)(Ch + (size_t)(m0 + row) * ldc + col);
            dst[0] = h01; dst[1] = h23;
        } else {
            *(float4*)(Cf + (size_t)(m0 + row) * ldc + col) = v;
        }
    }
}

// ---------------- host launch ----------------
extern "C" void kernel_launch(void* const* d_in, const int* in_sizes, int n_in,
                              void* d_out, int out_size) {
    const float* x      = (const float*)d_in[0];
    const float* r      = (const float*)d_in[1];
    const float* ln1_g  = (const float*)d_in[2];
    const float* ln1_b  = (const float*)d_in[3];
    const float* qkv_w  = (const float*)d_in[4];
    const float* qkv_b  = (const float*)d_in[5];
    const float* conv_w = (const float*)d_in[6];
    const float* conv_b = (const float*)d_in[7];
    const float* proj_w = (const float*)d_in[8];
    const float* proj_b = (const float*)d_in[9];
    const float* ln2_g  = (const float*)d_in[10];
    const float* ln2_b  = (const float*)d_in[11];
    const float* fc1_w  = (const float*)d_in[12];
    const float* fc1_b  = (const float*)d_in[13];
    const float* fc2_w  = (const float*)d_in[14];
    const float* fc2_b  = (const float*)d_in[15];

    float* out    = (float*)d_out;
    float* out_x  = out;
    float* out_am = out + (size_t)ROWS * DIMC;
    float* out_un = out_am + (size_t)BC * HEADSC * NN;

    __half *h_, *qkvh_, *qk_, *attn_, *av_, *h2_, *fc1_, *wqkv_, *wpro_, *wfc1_, *wfc2_;
    float  *x1_, *fc2p_;
    cudaGetSymbolAddress((void**)&h_,    g_h);
    cudaGetSymbolAddress((void**)&qkvh_, g_qkvh);
    cudaGetSymbolAddress((void**)&qk_,   g_qk);
    cudaGetSymbolAddress((void**)&attn_, g_attn);
    cudaGetSymbolAddress((void**)&av_,   g_av);
    cudaGetSymbolAddress((void**)&x1_,   g_x1);
    cudaGetSymbolAddress((void**)&h2_,   g_h2);
    cudaGetSymbolAddress((void**)&fc1_,  g_fc1);
    cudaGetSymbolAddress((void**)&fc2p_, g_fc2p);
    cudaGetSymbolAddress((void**)&wqkv_, g_wqkv);
    cudaGetSymbolAddress((void**)&wpro_, g_wpro);
    cudaGetSymbolAddress((void**)&wfc1_, g_wfc1);
    cudaGetSymbolAddress((void**)&wfc2_, g_wfc2);

    // smem sizes (bytes)
    const int SM_NT128_64 = 2 * (128 * 72 + 128 * 72) * 2;    // 73728
    const int SM_QK_32    = 128 * (128 + 4) * 4;              // 67584
    const int SM_AV_64    = 2 * (128 * 72 + 64 * 72) * 2;     // 55296

    auto setsm = [](const void* f, int bytes) {
        cudaFuncSetAttribute(f, cudaFuncAttributeMaxDynamicSharedMemorySize, bytes);
        cudaFuncSetAttribute(f, cudaFuncAttributePreferredSharedMemoryCarveout, 100);
    };
    setsm((const void*)gemm_h<64,128,0,1,1>, SM_NT128_64);
    setsm((const void*)gemm_h<32,128,0,0,1>, SM_QK_32);
    setsm((const void*)gemm_h<64,64,1,0,1>,  SM_AV_64);
    setsm((const void*)gemm_h<64,128,0,3,0>, SM_NT128_64);
    setsm((const void*)gemm_h<64,128,0,2,1>, SM_NT128_64);
    setsm((const void*)gemm_h<64,128,0,0,0>, SM_NT128_64);

    // 0. weight conversion (single launch)
    {
        int total4 = (W0 + W1 + W2 + W3) / 4;
        f2h_all<<<(total4 + 255) / 256, 256>>>(qkv_w, proj_w, fc1_w, fc2_w,
                                               wqkv_, wpro_, wfc1_, wfc2_);
    }

    // 1. ln1
    ln_kernel<<<ROWS, 256>>>(x, ln1_g, ln1_b, h_);

    // 2. qkv = h @ qkv_w^T + qkv_b -> half (BK=64)
    gemm_h<64,128,0,1,1><<<dim3(3 * DIMC / 128, ROWS / 128, 1), 256, SM_NT128_64>>>(
        h_, wqkv_, qkvh_, qkv_b, nullptr,
        DIMC, DIMC, DIMC, 3 * DIMC,
        0, 0, 0, 0, 0, 0, 1);

    // 3. qk = Q @ K^T -> half raw scores (BK=32)
    gemm_h<32,128,0,0,1><<<dim3(NC / 128, NC / 128, BC * HEADSC), 256, SM_QK_32>>>(
        qkvh_, qkvh_ + DIMC, qk_, nullptr, nullptr,
        HDC, 3 * DIMC, 3 * DIMC, NC,
        (long)NC * 3 * DIMC, HDC,
        (long)NC * 3 * DIMC, HDC,
        (long)HEADSC * NN, (long)NN,
        HEADSC);

    // 4. fused middle (streaming am/unc stores)
    mid_kernel<<<BC * NC, 256>>>(qk_, r, conv_w, conv_b, out_am, out_un, attn_);

    // 5. av = attn @ V -> half (BK=64)
    gemm_h<64,64,1,0,1><<<dim3(1, NC / 128, BC * HEADSC), 256, SM_AV_64>>>(
        attn_, qkvh_ + 2 * DIMC, av_, nullptr, nullptr,
        NC, NC, 3 * DIMC, DIMC,
        (long)HEADSC * NN, (long)NN,
        (long)NC * 3 * DIMC, HDC,
        (long)NC * DIMC, HDC,
        HEADSC);

    // 6. x1 = x + av @ proj_w^T + proj_b -> fp32 (fused, R13 config)
    gemm_h<64,128,0,3,0><<<dim3(DIMC / 128, ROWS / 128, 1), 256, SM_NT128_64>>>(
        av_, wpro_, x1_, proj_b, x,
        DIMC, DIMC, DIMC, DIMC,
        0, 0, 0, 0, 0, 0, 1);

    // 7. ln2
    ln_kernel<<<ROWS, 256>>>(x1_, ln2_g, ln2_b, h2_);

    // 8. fc1 = gelu(h2 @ fc1_w^T + fc1_b) -> half (BK=64)
    gemm_h<64,128,0,2,1><<<dim3(MLPC / 128, ROWS / 128, 1), 256, SM_NT128_64>>>(
        h2_, wfc1_, fc1_, fc1_b, nullptr,
        DIMC, DIMC, DIMC, MLPC,
        0, 0, 0, 0, 0, 0, 1);

    // 9a. fc2 split-K partials
    gemm_h<64,128,0,0,0><<<dim3(DIMC / 128, ROWS / 128, NSPLIT), 256, SM_NT128_64>>>(
        fc1_, wfc2_, fc2p_, nullptr, nullptr,
        MLPC / NSPLIT, MLPC, MLPC, DIMC,
        (long)(MLPC / NSPLIT), 0,
        (long)(MLPC / NSPLIT), 0,
        (long)ROWS * DIMC, 0,
        1);

    // 9b. out_x = x1 + fc2_b + sum partials
    splitk_reduce_kernel<NSPLIT><<<ROWS * DIMC / 4 / 256, 256>>>(fc2p_, x1_, fc2_b, out_x);
}

// round 17
// speedup vs baseline: 1.0466x; 1.0124x over previous
#include <cuda_runtime.h>
#include <cuda_fp16.h>
#include <mma.h>
#include <math.h>

using namespace nvcuda;

#define DIMC   768
#define HEADSC 12
#define HDC    64
#define BC     2
#define NC     1024
#define MLPC   3072
#define ROWS   (BC * NC)
#define NN     (NC * NC)
#define SCALEC 0.125f
#define NSPLIT 4

// ---------------- scratch ----------------
__device__ __half g_h   [ROWS * DIMC];
__device__ __half g_qkvh[ROWS * 3 * DIMC];
__device__ __half g_qk  [(size_t)BC * HEADSC * NN];
__device__ __half g_attn[(size_t)BC * HEADSC * NN];
__device__ __half g_av  [ROWS * DIMC];
__device__ float  g_x1  [ROWS * DIMC];
__device__ __half g_h2  [ROWS * DIMC];
__device__ __half g_fc1 [ROWS * MLPC];
__device__ float  g_fc2p[NSPLIT * ROWS * DIMC];
__device__ __half g_wqkv[3 * DIMC * DIMC];
__device__ __half g_wpro[DIMC * DIMC];
__device__ __half g_wfc1[MLPC * DIMC];
__device__ __half g_wfc2[DIMC * MLPC];

#define W0 (3 * DIMC * DIMC)
#define W1 (DIMC * DIMC)
#define W2 (MLPC * DIMC)
#define W3 (DIMC * MLPC)
#define F2H_BLOCKS ((W0 + W1 + W2 + W3) / 4 / 256)   // 9216

// ------ merged: ln1 (blocks 0..ROWS-1) + weight fp32->fp16 (rest) ------
__global__ void f2h_ln1_kernel(const float* __restrict__ wa, const float* __restrict__ wb,
                               const float* __restrict__ wc, const float* __restrict__ wd,
                               __half* __restrict__ oa, __half* __restrict__ ob,
                               __half* __restrict__ oc, __half* __restrict__ od,
                               const float* __restrict__ x, const float* __restrict__ g,
                               const float* __restrict__ b, __half* __restrict__ y) {
    if (blockIdx.x >= ROWS) {
        // weight conversion
        size_t i4 = (size_t)(blockIdx.x - ROWS) * 256 + threadIdx.x;
        size_t i  = i4 * 4;
        const float* src; __half* dst; size_t off;
        if (i < W0)                     { src = wa; dst = oa; off = i; }
        else if (i < W0 + W1)           { src = wb; dst = ob; off = i - W0; }
        else if (i < W0 + W1 + W2)      { src = wc; dst = oc; off = i - W0 - W1; }
        else if (i < W0 + W1 + W2 + W3) { src = wd; dst = od; off = i - W0 - W1 - W2; }
        else return;
        float4 v = *(const float4*)(src + off);
        __half2* o2 = (__half2*)(dst + off);
        o2[0] = __floats2half2_rn(v.x, v.y);
        o2[1] = __floats2half2_rn(v.z, v.w);
        return;
    }
    // layernorm row
    int row = blockIdx.x;
    const float* xr = x + (size_t)row * DIMC;
    __half*      yr = y + (size_t)row * DIMC;
    float v[3];
    float s = 0.f, s2 = 0.f;
#pragma unroll
    for (int i = 0; i < 3; i++) {
        v[i] = xr[threadIdx.x + 256 * i];
        s += v[i]; s2 += v[i] * v[i];
    }
    __shared__ float sh[16];
#pragma unroll
    for (int o = 16; o; o >>= 1) {
        s  += __shfl_xor_sync(~0u, s,  o);
        s2 += __shfl_xor_sync(~0u, s2, o);
    }
    int w = threadIdx.x >> 5;
    if ((threadIdx.x & 31) == 0) { sh[w] = s; sh[8 + w] = s2; }
    __syncthreads();
    if (threadIdx.x < 32) {
        s  = threadIdx.x < 8 ? sh[threadIdx.x]     : 0.f;
        s2 = threadIdx.x < 8 ? sh[8 + threadIdx.x] : 0.f;
#pragma unroll
        for (int o = 4; o; o >>= 1) {
            s  += __shfl_xor_sync(~0u, s,  o);
            s2 += __shfl_xor_sync(~0u, s2, o);
        }
        if (threadIdx.x == 0) { sh[0] = s; sh[1] = s2; }
    }
    __syncthreads();
    float mean = sh[0] * (1.f / DIMC);
    float var  = sh[1] * (1.f / DIMC) - mean * mean;
    float rstd = rsqrtf(var + 1e-5f);
#pragma unroll
    for (int i = 0; i < 3; i++) {
        int c = threadIdx.x + 256 * i;
        yr[c] = __float2half_rn((v[i] - mean) * rstd * g[c] + b[c]);
    }
}

// ---------------- layernorm (half out) ----------------
__global__ void ln_kernel(const float* __restrict__ x, const float* __restrict__ g,
                          const float* __restrict__ b, __half* __restrict__ y) {
    int row = blockIdx.x;
    const float* xr = x + (size_t)row * DIMC;
    __half*      yr = y + (size_t)row * DIMC;
    float v[3];
    float s = 0.f, s2 = 0.f;
#pragma unroll
    for (int i = 0; i < 3; i++) {
        v[i] = xr[threadIdx.x + 256 * i];
        s += v[i]; s2 += v[i] * v[i];
    }
    __shared__ float sh[16];
#pragma unroll
    for (int o = 16; o; o >>= 1) {
        s  += __shfl_xor_sync(~0u, s,  o);
        s2 += __shfl_xor_sync(~0u, s2, o);
    }
    int w = threadIdx.x >> 5;
    if ((threadIdx.x & 31) == 0) { sh[w] = s; sh[8 + w] = s2; }
    __syncthreads();
    if (threadIdx.x < 32) {
        s  = threadIdx.x < 8 ? sh[threadIdx.x]     : 0.f;
        s2 = threadIdx.x < 8 ? sh[8 + threadIdx.x] : 0.f;
#pragma unroll
        for (int o = 4; o; o >>= 1) {
            s  += __shfl_xor_sync(~0u, s,  o);
            s2 += __shfl_xor_sync(~0u, s2, o);
        }
        if (threadIdx.x == 0) { sh[0] = s; sh[1] = s2; }
    }
    __syncthreads();
    float mean = sh[0] * (1.f / DIMC);
    float var  = sh[1] * (1.f / DIMC) - mean * mean;
    float rstd = rsqrtf(var + 1e-5f);
#pragma unroll
    for (int i = 0; i < 3; i++) {
        int c = threadIdx.x + 256 * i;
        yr[c] = __float2half_rn((v[i] - mean) * rstd * g[c] + b[c]);
    }
}

// ------ fused middle (loads split into 2 groups of 6 to cap MLP_p1) ------
__global__ __launch_bounds__(256)
void mid_kernel(const __half* __restrict__ qk, const float* __restrict__ r,
                const float* __restrict__ cw, const float* __restrict__ cb,
                float* __restrict__ am, float* __restrict__ unc,
                __half* __restrict__ attn) {
    __shared__ float scw[HEADSC * HEADSC];
    __shared__ float scb[HEADSC];
    __shared__ float red[8 * HEADSC];
    __shared__ float fmx[HEADSC];
    __shared__ float fnv[HEADSC];

    int t  = threadIdx.x;
    int bn = blockIdx.x;
    int b  = bn >> 10, n = bn & 1023;
    if (t < HEADSC * HEADSC) scw[t] = cw[t];
    if (t < HEADSC)          scb[t] = cb[t];

    size_t base = (((size_t)b * HEADSC) << 20) + ((size_t)n << 10) + t * 4;

    float4 sv[HEADSC];
    // group 1: load heads 0..5 then consume (max reduce waits on these loads)
#pragma unroll
    for (int h = 0; h < 6; h++) {
        const __half2* qp = (const __half2*)(qk + base + ((size_t)h << 20));
        __half2 q0 = qp[0], q1 = qp[1];
        float2 f0 = __half22float2(q0), f1 = __half22float2(q1);
        sv[h] = make_float4(f0.x, f0.y, f1.x, f1.y);
    }
#pragma unroll
    for (int h = 0; h < 6; h++) {
        float m = fmaxf(fmaxf(sv[h].x, sv[h].y), fmaxf(sv[h].z, sv[h].w));
#pragma unroll
        for (int o = 16; o; o >>= 1) m = fmaxf(m, __shfl_xor_sync(~0u, m, o));
        if ((t & 31) == 0) red[(t >> 5) * HEADSC + h] = m;
    }
    // group 2: load heads 6..11 then consume
#pragma unroll
    for (int h = 6; h < HEADSC; h++) {
        const __half2* qp = (const __half2*)(qk + base + ((size_t)h << 20));
        __half2 q0 = qp[0], q1 = qp[1];
        float2 f0 = __half22float2(q0), f1 = __half22float2(q1);
        sv[h] = make_float4(f0.x, f0.y, f1.x, f1.y);
    }
#pragma unroll
    for (int h = 6; h < HEADSC; h++) {
        float m = fmaxf(fmaxf(sv[h].x, sv[h].y), fmaxf(sv[h].z, sv[h].w));
#pragma unroll
        for (int o = 16; o; o >>= 1) m = fmaxf(m, __shfl_xor_sync(~0u, m, o));
        if ((t & 31) == 0) red[(t >> 5) * HEADSC + h] = m;
    }
    __syncthreads();
    if (t < HEADSC) {
        float m = red[t];
#pragma unroll
        for (int ww = 1; ww < 8; ww++) m = fmaxf(m, red[ww * HEADSC + t]);
        fmx[t] = m * SCALEC;
    }
    __syncthreads();

#pragma unroll
    for (int h = 0; h < HEADSC; h++) {
        float mm = fmx[h];
        float s = __expf(sv[h].x * SCALEC - mm) + __expf(sv[h].y * SCALEC - mm)
                + __expf(sv[h].z * SCALEC - mm) + __expf(sv[h].w * SCALEC - mm);
#pragma unroll
        for (int o = 16; o; o >>= 1) s += __shfl_xor_sync(~0u, s, o);
        if ((t & 31) == 0) red[(t >> 5) * HEADSC + h] = s;
    }
    __syncthreads();
    if (t < HEADSC) {
        float s = 0.f;
#pragma unroll
        for (int ww = 0; ww < 8; ww++) s += red[ww * HEADSC + t];
        fnv[t] = 1.f / s;
    }
    __syncthreads();

#pragma unroll
    for (int g = 0; g < HEADSC; g++) {
        float ax = scb[g], ay = scb[g], az = scb[g], aw = scb[g];
#pragma unroll
        for (int h = 0; h < HEADSC; h++) {
            float wv = scw[g * HEADSC + h];
            ax += wv * sv[h].x; ay += wv * sv[h].y;
            az += wv * sv[h].z; aw += wv * sv[h].w;
        }
        float4 u;
        u.x = 1.f / (1.f + __expf(-ax));
        u.y = 1.f / (1.f + __expf(-ay));
        u.z = 1.f / (1.f + __expf(-az));
        u.w = 1.f / (1.f + __expf(-aw));
        float mm = fmx[g], iv = fnv[g];
        float4 p;
        p.x = __expf(sv[g].x * SCALEC - mm) * iv;
        p.y = __expf(sv[g].y * SCALEC - mm) * iv;
        p.z = __expf(sv[g].z * SCALEC - mm) * iv;
        p.w = __expf(sv[g].w * SCALEC - mm) * iv;
        size_t o = base + ((size_t)g << 20);
        float4 rv = *(const float4*)(r + o);
        __stwt((float4*)(am + o), p);
        __stwt((float4*)(unc + o), u);
        __half2* at = (__half2*)(attn + o);
        at[0] = __floats2half2_rn(p.x + u.x * rv.x, p.y + u.y * rv.y);
        at[1] = __floats2half2_rn(p.z + u.z * rv.z, p.w + u.w * rv.w);
    }
}

// ------ split-K reduce ------
template<int NS>
__global__ void splitk_reduce_kernel(const float* __restrict__ part,
                                     const float* __restrict__ res,
                                     const float* __restrict__ bias,
                                     float* __restrict__ out) {
    size_t i = ((size_t)blockIdx.x * 256 + threadIdx.x) * 4;
    int col = (int)(i % DIMC);
    float4 v  = *(const float4*)(res + i);
    float4 bv = *(const float4*)(bias + col);
    v.x += bv.x; v.y += bv.y; v.z += bv.z; v.w += bv.w;
#pragma unroll
    for (int s = 0; s < NS; s++) {
        float4 p = *(const float4*)(part + (size_t)s * ROWS * DIMC + i);
        v.x += p.x; v.y += p.y; v.z += p.z; v.w += p.w;
    }
    *(float4*)(out + i) = v;
}

// ---------------- fp16 tensor-core GEMM (2-stage cp.async, templated BK) ----------------
__device__ __forceinline__ void cpa16h(__half* dst, const __half* src) {
    unsigned s = (unsigned)__cvta_generic_to_shared(dst);
    asm volatile("cp.async.cg.shared.global [%0], [%1], 16;" :: "r"(s), "l"(src));
}

template<int BK, int BN, int BLAY, int EPI, int OUTH>
__global__ __launch_bounds__(256)
void gemm_h(const __half* __restrict__ A, const __half* __restrict__ B,
            void* __restrict__ Cv, const float* __restrict__ bias,
            const float* __restrict__ res,
            int K, int lda, int ldb, int ldc,
            long sAb, long sAh, long sBb, long sBh, long sCb, long sCh,
            int Hdiv) {
    constexpr int BM  = 128;
    constexpr int LDS = BK + 8;
    constexpr int WN  = BN / 2;
    constexpr int NFR = WN / 16;
    constexpr int ASZ = BM * LDS;
    constexpr int LDB_S = (BLAY == 0) ? LDS : (BN + 8);
    constexpr int BSZ = (BLAY == 0) ? BN * LDS : BK * LDB_S;
    constexpr int CPR = BK / 8;

    extern __shared__ __half smem[];
    __half* As[2] = { smem,       smem + ASZ + BSZ };
    __half* Bs[2] = { smem + ASZ, smem + 2 * ASZ + BSZ };

    int z  = blockIdx.z;
    int zb = z / Hdiv, zh = z % Hdiv;
    A += zb * sAb + zh * sAh;
    B += zb * sBb + zh * sBh;
    size_t coff = (size_t)zb * sCb + (size_t)zh * sCh;
    float*  Cf = (float*)Cv + coff;
    __half* Ch = (__half*)Cv + coff;
    if (EPI == 3) res += coff;

    int m0 = blockIdx.y * BM, n0 = blockIdx.x * BN;
    int t   = threadIdx.x;
    int wid = t >> 5;
    int wm  = wid & 3;
    int wn  = wid >> 2;

    wmma::fragment<wmma::accumulator, 16, 16, 16, float> acc[2][NFR];
#pragma unroll
    for (int i = 0; i < 2; i++)
#pragma unroll
        for (int j = 0; j < NFR; j++) wmma::fill_fragment(acc[i][j], 0.f);

    const int stages = K / BK;

    auto load_tiles = [&](int k0, int st) {
#pragma unroll
        for (int i = 0; i < BM * BK / 8 / 256; i++) {
            int f   = t + i * 256;
            int row = f / CPR;
            int c8  = (f % CPR) * 8;
            cpa16h(As[st] + row * LDS + c8,
                   A + (size_t)(m0 + row) * lda + k0 + c8);
        }
        if (BLAY == 0) {
#pragma unroll
            for (int i = 0; i < BN * BK / 8 / 256; i++) {
                int f   = t + i * 256;
                int row = f / CPR;
                int c8  = (f % CPR) * 8;
                cpa16h(Bs[st] + row * LDS + c8,
                       B + (size_t)(n0 + row) * ldb + k0 + c8);
            }
        } else {
#pragma unroll
            for (int i = 0; i < BK * BN / 8 / 256; i++) {
                int f   = t + i * 256;
                int row = f / (BN / 8);
                int c8  = (f % (BN / 8)) * 8;
                cpa16h(Bs[st] + row * LDB_S + c8,
                       B + (size_t)(k0 + row) * ldb + n0 + c8);
            }
        }
        asm volatile("cp.async.commit_group;" ::: "memory");
    };

    load_tiles(0, 0);

    for (int it = 0; it < stages; ++it) {
        int cur = it & 1;
        if (it + 1 < stages) {
            load_tiles((it + 1) * BK, cur ^ 1);
            asm volatile("cp.async.wait_group 1;" ::: "memory");
        } else {
            asm volatile("cp.async.wait_group 0;" ::: "memory");
        }
        __syncthreads();

        const __half* as = As[cur];
        const __half* bs = Bs[cur];
#pragma unroll
        for (int kk = 0; kk < BK; kk += 16) {
            wmma::fragment<wmma::matrix_a, 16, 16, 16, __half, wmma::row_major> af[2];
#pragma unroll
            for (int i = 0; i < 2; i++)
                wmma::load_matrix_sync(af[i], as + (wm * 32 + i * 16) * LDS + kk, LDS);
            if (BLAY == 0) {
#pragma unroll
                for (int j = 0; j < NFR; j++) {
                    wmma::fragment<wmma::matrix_b, 16, 16, 16, __half, wmma::col_major> bf;
                    wmma::load_matrix_sync(bf, bs + (wn * WN + j * 16) * LDS + kk, LDS);
#pragma unroll
                    for (int i = 0; i < 2; i++)
                        wmma::mma_sync(acc[i][j], af[i], bf, acc[i][j]);
                }
            } else {
#pragma unroll
                for (int j = 0; j < NFR; j++) {
                    wmma::fragment<wmma::matrix_b, 16, 16, 16, __half, wmma::row_major> bf;
                    wmma::load_matrix_sync(bf, bs + kk * LDB_S + wn * WN + j * 16, LDB_S);
#pragma unroll
                    for (int i = 0; i < 2; i++)
                        wmma::mma_sync(acc[i][j], af[i], bf, acc[i][j]);
                }
            }
        }
        __syncthreads();
    }

    if (EPI == 0 && OUTH == 0) {
#pragma unroll
        for (int i = 0; i < 2; i++)
#pragma unroll
            for (int j = 0; j < NFR; j++)
                wmma::store_matrix_sync(
                    Cf + (size_t)(m0 + wm * 32 + i * 16) * ldc + n0 + wn * WN + j * 16,
                    acc[i][j], ldc, wmma::mem_row_major);
        return;
    }

    constexpr int LDC_S = BN + 4;
    float* Cs = (float*)smem;
#pragma unroll
    for (int i = 0; i < 2; i++)
#pragma unroll
        for (int j = 0; j < NFR; j++)
            wmma::store_matrix_sync(Cs + (wm * 32 + i * 16) * LDC_S + wn * WN + j * 16,
                                    acc[i][j], LDC_S, wmma::mem_row_major);
    __syncthreads();

#pragma unroll
    for (int i = 0; i < BM * BN / 4 / 256; i++) {
        int f4  = t + i * 256;
        int row = f4 / (BN / 4);
        int c4  = (f4 % (BN / 4)) * 4;
        float4 v = *(const float4*)(Cs + row * LDC_S + c4);
        int col = n0 + c4;
        if (EPI >= 1) {
            float4 bv = *(const float4*)(bias + col);
            v.x += bv.x; v.y += bv.y; v.z += bv.z; v.w += bv.w;
        }
        if (EPI == 2) {
            float* p = &v.x;
#pragma unroll
            for (int e = 0; e < 4; e++) {
                float u = p[e];
                p[e] = 0.5f * u * (1.f + tanhf(0.7978845608f * (u + 0.044715f * u * u * u)));
            }
        }
        if (EPI == 3) {
            float4 rv = *(const float4*)(res + (size_t)(m0 + row) * ldc + col);
            v.x += rv.x; v.y += rv.y; v.z += rv.z; v.w += rv.w;
        }
        if (OUTH) {
            __half2 h01 = __floats2half2_rn(v.x, v.y);
            __half2 h23 = __floats2half2_rn(v.z, v.w);
            __half2* dst = (__half2*)(Ch + (size_t)(m0 + row) * ldc + col);
            dst[0] = h01; dst[1] = h23;
        } else {
            *(float4*)(Cf + (size_t)(m0 + row) * ldc + col) = v;
        }
    }
}

// ---------------- host launch ----------------
extern "C" void kernel_launch(void* const* d_in, const int* in_sizes, int n_in,
                              void* d_out, int out_size) {
    const float* x      = (const float*)d_in[0];
    const float* r      = (const float*)d_in[1];
    const float* ln1_g  = (const float*)d_in[2];
    const float* ln1_b  = (const float*)d_in[3];
    const float* qkv_w  = (const float*)d_in[4];
    const float* qkv_b  = (const float*)d_in[5];
    const float* conv_w = (const float*)d_in[6];
    const float* conv_b = (const float*)d_in[7];
    const float* proj_w = (const float*)d_in[8];
    const float* proj_b = (const float*)d_in[9];
    const float* ln2_g  = (const float*)d_in[10];
    const float* ln2_b  = (const float*)d_in[11];
    const float* fc1_w  = (const float*)d_in[12];
    const float* fc1_b  = (const float*)d_in[13];
    const float* fc2_w  = (const float*)d_in[14];
    const float* fc2_b  = (const float*)d_in[15];

    float* out    = (float*)d_out;
    float* out_x  = out;
    float* out_am = out + (size_t)ROWS * DIMC;
    float* out_un = out_am + (size_t)BC * HEADSC * NN;

    __half *h_, *qkvh_, *qk_, *attn_, *av_, *h2_, *fc1_, *wqkv_, *wpro_, *wfc1_, *wfc2_;
    float  *x1_, *fc2p_;
    cudaGetSymbolAddress((void**)&h_,    g_h);
    cudaGetSymbolAddress((void**)&qkvh_, g_qkvh);
    cudaGetSymbolAddress((void**)&qk_,   g_qk);
    cudaGetSymbolAddress((void**)&attn_, g_attn);
    cudaGetSymbolAddress((void**)&av_,   g_av);
    cudaGetSymbolAddress((void**)&x1_,   g_x1);
    cudaGetSymbolAddress((void**)&h2_,   g_h2);
    cudaGetSymbolAddress((void**)&fc1_,  g_fc1);
    cudaGetSymbolAddress((void**)&fc2p_, g_fc2p);
    cudaGetSymbolAddress((void**)&wqkv_, g_wqkv);
    cudaGetSymbolAddress((void**)&wpro_, g_wpro);
    cudaGetSymbolAddress((void**)&wfc1_, g_wfc1);
    cudaGetSymbolAddress((void**)&wfc2_, g_wfc2);

    // smem sizes (bytes)
    const int SM_NT128_64 = 2 * (128 * 72 + 128 * 72) * 2;    // 73728
    const int SM_QK_32    = 128 * (128 + 4) * 4;              // 67584
    const int SM_AV_64    = 2 * (128 * 72 + 64 * 72) * 2;     // 55296

    auto setsm = [](const void* f, int bytes) {
        cudaFuncSetAttribute(f, cudaFuncAttributeMaxDynamicSharedMemorySize, bytes);
        cudaFuncSetAttribute(f, cudaFuncAttributePreferredSharedMemoryCarveout, 100);
    };
    setsm((const void*)gemm_h<64,128,0,1,1>, SM_NT128_64);
    setsm((const void*)gemm_h<32,128,0,0,1>, SM_QK_32);
    setsm((const void*)gemm_h<64,64,1,0,1>,  SM_AV_64);
    setsm((const void*)gemm_h<64,128,0,3,0>, SM_NT128_64);
    setsm((const void*)gemm_h<64,128,0,2,1>, SM_NT128_64);
    setsm((const void*)gemm_h<64,128,0,0,0>, SM_NT128_64);

    // 0+1. merged weight conversion + ln1
    f2h_ln1_kernel<<<ROWS + F2H_BLOCKS, 256>>>(
        qkv_w, proj_w, fc1_w, fc2_w, wqkv_, wpro_, wfc1_, wfc2_,
        x, ln1_g, ln1_b, h_);

    // 2. qkv = h @ qkv_w^T + qkv_b -> half (BK=64)
    gemm_h<64,128,0,1,1><<<dim3(3 * DIMC / 128, ROWS / 128, 1), 256, SM_NT128_64>>>(
        h_, wqkv_, qkvh_, qkv_b, nullptr,
        DIMC, DIMC, DIMC, 3 * DIMC,
        0, 0, 0, 0, 0, 0, 1);

    // 3. qk = Q @ K^T -> half raw scores (BK=32)
    gemm_h<32,128,0,0,1><<<dim3(NC / 128, NC / 128, BC * HEADSC), 256, SM_QK_32>>>(
        qkvh_, qkvh_ + DIMC, qk_, nullptr, nullptr,
        HDC, 3 * DIMC, 3 * DIMC, NC,
        (long)NC * 3 * DIMC, HDC,
        (long)NC * 3 * DIMC, HDC,
        (long)HEADSC * NN, (long)NN,
        HEADSC);

    // 4. fused middle (split load groups)
    mid_kernel<<<BC * NC, 256>>>(qk_, r, conv_w, conv_b, out_am, out_un, attn_);

    // 5. av = attn @ V -> half (BK=64)
    gemm_h<64,64,1,0,1><<<dim3(1, NC / 128, BC * HEADSC), 256, SM_AV_64>>>(
        attn_, qkvh_ + 2 * DIMC, av_, nullptr, nullptr,
        NC, NC, 3 * DIMC, DIMC,
        (long)HEADSC * NN, (long)NN,
        (long)NC * 3 * DIMC, HDC,
        (long)NC * DIMC, HDC,
        HEADSC);

    // 6. x1 = x + av @ proj_w^T + proj_b -> fp32
    gemm_h<64,128,0,3,0><<<dim3(DIMC / 128, ROWS / 128, 1), 256, SM_NT128_64>>>(
        av_, wpro_, x1_, proj_b, x,
        DIMC, DIMC, DIMC, DIMC,
        0, 0, 0, 0, 0, 0, 1);

    // 7. ln2
    ln_kernel<<<ROWS, 256>>>(x1_, ln2_g, ln2_b, h2_);

    // 8. fc1 = gelu(h2 @ fc1_w^T + fc1_b) -> half (BK=64)
    gemm_h<64,128,0,2,1><<<dim3(MLPC / 128, ROWS / 128, 1), 256, SM_NT128_64>>>(
        h2_, wfc1_, fc1_, fc1_b, nullptr,
        DIMC, DIMC, DIMC, MLPC,
        0, 0, 0, 0, 0, 0, 1);

    // 9a. fc2 split-K partials
    gemm_h<64,128,0,0,0><<<dim3(DIMC / 128, ROWS / 128, NSPLIT), 256, SM_NT128_64>>>(
        fc1_, wfc2_, fc2p_, nullptr, nullptr,
        MLPC / NSPLIT, MLPC, MLPC, DIMC,
        (long)(MLPC / NSPLIT), 0,
        (long)(MLPC / NSPLIT), 0,
        (long)ROWS * DIMC, 0,
        1);

    // 9b. out_x = x1 + fc2_b + sum partials
    splitk_reduce_kernel<NSPLIT><<<ROWS * DIMC / 4 / 256, 256>>>(fc2p_, x1_, fc2_b, out_x);
}